// round 11
// baseline (speedup 1.0000x reference)
#include <cuda_runtime.h>

// SinusoidalEmbedding: out[b][s][d] = emb_table[x[b][s]][d] + PE[s][d]
// PE[s][2i] = sin(s*f_i), PE[s][2i+1] = cos(s*f_i), f_i = 10000^(-2i/1024)
//
// R11: exact R7 shape (best so far: 2 positions/CTA, 256 thr, v8 accesses,
// regs 40). SINGLE change: output stores are st.global.cs.v8 (evict-first).
// Rationale: writes are 134MB of the 196MB DRAM traffic and are never read;
// with default policy they write-allocate in L2 and evict emb-table rows,
// forcing ~62MB of read misses. R3's .cs test was confounded (batching +
// forced occupancy); this is the clean test.

#define BQ      8
#define S_LEN   4096
#define D_M     1024
#define TPB     256
#define POS_PER_CTA 2

__device__ __forceinline__ void ldg_v8(const float* p, float* v) {
    unsigned r0, r1, r2, r3, r4, r5, r6, r7;
    asm volatile("ld.global.nc.v8.b32 {%0,%1,%2,%3,%4,%5,%6,%7}, [%8];"
                 : "=r"(r0), "=r"(r1), "=r"(r2), "=r"(r3),
                   "=r"(r4), "=r"(r5), "=r"(r6), "=r"(r7)
                 : "l"(p));
    v[0] = __uint_as_float(r0); v[1] = __uint_as_float(r1);
    v[2] = __uint_as_float(r2); v[3] = __uint_as_float(r3);
    v[4] = __uint_as_float(r4); v[5] = __uint_as_float(r5);
    v[6] = __uint_as_float(r6); v[7] = __uint_as_float(r7);
}

__device__ __forceinline__ void stg_cs_v8(float* p, const float* v) {
    asm volatile("st.global.cs.v8.b32 [%0], {%1,%2,%3,%4,%5,%6,%7,%8};"
                 :: "l"(p),
                    "r"(__float_as_uint(v[0])), "r"(__float_as_uint(v[1])),
                    "r"(__float_as_uint(v[2])), "r"(__float_as_uint(v[3])),
                    "r"(__float_as_uint(v[4])), "r"(__float_as_uint(v[5])),
                    "r"(__float_as_uint(v[6])), "r"(__float_as_uint(v[7]))
                 : "memory");
}

__global__ __launch_bounds__(TPB)
void sinemb_kernel(const void* __restrict__ xraw,
                   const float* __restrict__ emb,
                   float* __restrict__ out)
{
    const int t    = threadIdx.x;
    const int lane = t & 127;                        // owns floats 8*lane..+7
    const int s    = blockIdx.x * POS_PER_CTA + (t >> 7);  // position

    // ---- index dtype detect (int64 vs int32) ----
    const unsigned int* w = (const unsigned int*)xraw;
    const bool is64 = ((w[1] | w[3] | w[5] | w[7]) == 0u);

    // ---- gather rows for this position across the batch ----
    int rows[BQ];
    if (is64) {
        const long long* x64 = (const long long*)xraw;
        #pragma unroll
        for (int b = 0; b < BQ; b++) rows[b] = (int)x64[(long long)b * S_LEN + s];
    } else {
        const int* x32 = (const int*)xraw;
        #pragma unroll
        for (int b = 0; b < BQ; b++) rows[b] = x32[b * S_LEN + s];
    }

    // ---- PE: 4 (sin,cos) pairs for this thread's 8 floats ----
    // pair i -> frequency index 4*lane+i; f = 2^(c_exp * idx)
    const float c_exp = -0.02595256324130752f;
    const float fs = (float)s;
    float p[8];
    #pragma unroll
    for (int i = 0; i < 4; i++) {
        float f = exp2f(c_exp * (float)(4 * lane + i));
        sincosf(fs * f, &p[2 * i], &p[2 * i + 1]);
    }

    // ---- gather (default policy) + add + store (.cs evict-first) ----
    #pragma unroll
    for (int b = 0; b < BQ; b++) {
        float e[8];
        ldg_v8(emb + (long long)rows[b] * D_M + 8 * lane, e);
        float o[8];
        #pragma unroll
        for (int i = 0; i < 8; i++) o[i] = e[i] + p[i];
        stg_cs_v8(out + ((long long)b * S_LEN + s) * D_M + 8 * lane, o);
    }
}

extern "C" void kernel_launch(void* const* d_in, const int* in_sizes, int n_in,
                              void* d_out, int out_size)
{
    const void*  x   = d_in[0];                 // [8, 4096] int64 (or int32)
    const float* emb = (const float*)d_in[1];   // [50257, 1024] fp32
    float*       out = (float*)d_out;           // [8, 4096, 1024] fp32

    sinemb_kernel<<<S_LEN / POS_PER_CTA, TPB>>>(x, emb, out);
}